// round 16
// baseline (speedup 1.0000x reference)
#include <cuda_runtime.h>
#include <cuda_fp16.h>

// WarpingLayer v16: single persistent kernel, atomic work-stealing pipeline.
//   Work items (16384): [T(0) x1024][T(1)/G(0) interleaved x2048]...[G(7) x1024]
//   T(b,vb): transpose one 32c x 128hw tile of batch b (NCHW f32 -> NHWC f16).
//   G(b,vb): gather 32 pixels of batch b from xt (in-block param compute,
//            pixel-pair uint4 corner loads, swizzled fp16 staging, coalesced
//            STG.32 writeback). G(b) spin-waits on g_done[b]==1024 (release
//            via per-thread threadfence + block count; acquire via volatile
//            spin + threadfence). Counter order => T(b) fully claimed before
//            any G(b) claim => deadlock-free at any residency.
// Param math reproduces the JAX reference fp32 op ordering exactly.

namespace {

constexpr int B = 8;
constexpr int C = 128;
constexpr int H = 128;
constexpr int W = 256;
constexpr int HW = H * W;                      // 32768
constexpr int RS = 67;                         // staging row stride (words)
constexpr unsigned NITEMS = 16384;             // 8192 T + 8192 G
constexpr int GRID = 1036;                     // 148 SMs x 7 blocks

// Scratch / pipeline state (__device__ globals: allowed).
__device__ __half   g_xt[(size_t)B * HW * C];  // 67 MB transposed image
__device__ unsigned g_ctr;                     // work-item counter
__device__ unsigned g_done[B];                 // transpose tiles done per batch

// ---------------- reset (runs first each call; graph-replay safe) -----------
__global__ void reset_kernel()
{
    g_ctr = 0;
    #pragma unroll
    for (int i = 0; i < B; ++i) g_done[i] = 0;
}

// ---------------- transpose item: tile vb of batch b ----------------
__device__ __forceinline__ void do_transpose(const float* __restrict__ x,
                                             int b, int vb, char* smem)
{
    float (*tile)[133] = (float(*)[133])smem;
    const int hw0 = (vb & 255) * 128;          // 256 hw-tiles
    const int c0  = (vb >> 8) * 32;            // 4 c-tiles
    const int tx  = threadIdx.x & 31;
    const int ty  = threadIdx.x >> 5;          // 0..7

    const float* px = x + (size_t)b * C * HW;
    #pragma unroll
    for (int i = 0; i < 4; ++i) {
        const int cl = ty + i * 8;             // 0..31
        const float4 v = __ldcs((const float4*)(px + (size_t)(c0 + cl) * HW + hw0) + tx);
        float* t = &tile[cl][4 * tx];
        t[0] = v.x; t[1] = v.y; t[2] = v.z; t[3] = v.w;
    }
    __syncthreads();

    __half* pt = g_xt + (size_t)b * HW * C;
    const int cpair = tx & 15;                 // channel pair 0..15
    const int hwsub = tx >> 4;                 // 0..1
    #pragma unroll
    for (int i = 0; i < 8; ++i) {
        const int hwl = (i * 8 + ty) * 2 + hwsub;          // 0..127
        const __half2 hv = __floats2half2_rn(tile[cpair * 2][hwl],
                                             tile[cpair * 2 + 1][hwl]);
        *(__half2*)(pt + (size_t)(hw0 + hwl) * C + c0 + cpair * 2) = hv;
    }
}

// ---------------- gather item: 32 pixels (vb) of batch b ----------------
__device__ __forceinline__ void do_gather(const float* __restrict__ flow,
                                          float* __restrict__ out,
                                          int b, int vb, char* smem)
{
    float4*   sw    = (float4*)smem;                       // 512 B
    int*      so    = (int*)(smem + 512);                  // 128 B
    unsigned* stile = (unsigned*)(smem + 640);             // 8576 B

    const int tid  = threadIdx.x;
    const int warp = tid >> 5;
    const int lane = tid & 31;
    const int li   = lane & 15;
    const int hf   = lane >> 4;                // 0: pixel A, 1: pixel B

    const int pix = vb * 32;                   // within batch b
    const int h  = pix >> 8;
    const int w0 = pix & (W - 1);

    // ---- warp 0: params for the block's 32 pixels (lane = pixel) ----
    if (warp == 0) {
        const int w = w0 + lane;
        const int fbase = b * 2 * HW + h * W + w;
        const float fx = __ldg(flow + fbase);
        const float fy = __ldg(flow + fbase + HW);

        // Reference-exact fp32 ordering:
        const float flo_w = __fmul_rn(__fdiv_rn(__fmul_rn(fx, 2.0f), (float)(W - 1)), 1.0f);
        const float flo_h = __fmul_rn(__fdiv_rn(__fmul_rn(fy, 2.0f), (float)(H - 1)), 1.0f);
        const float step_x = __fdiv_rn(2.0f, (float)(W - 1));
        const float step_y = __fdiv_rn(2.0f, (float)(H - 1));
        const float gx = __fadd_rn(-1.0f, __fmul_rn((float)w, step_x));
        const float gy = __fadd_rn(-1.0f, __fmul_rn((float)h, step_y));

        const float ix = __fmul_rn(__fmul_rn(__fadd_rn(__fadd_rn(gx, flo_w), 1.0f), 0.5f), (float)(W - 1));
        const float iy = __fmul_rn(__fmul_rn(__fadd_rn(__fadd_rn(gy, flo_h), 1.0f), 0.5f), (float)(H - 1));

        const float x0f = floorf(ix);
        const float y0f = floorf(iy);
        const float x1f = __fadd_rn(x0f, 1.0f);
        const float y1f = __fadd_rn(y0f, 1.0f);

        const float wx1 = __fadd_rn(ix, -x0f);
        const float wx0 = __fadd_rn(1.0f, -wx1);
        const float wy1 = __fadd_rn(iy, -y0f);
        const float wy0 = __fadd_rn(1.0f, -wy1);

        const bool vx0 = (x0f >= 0.0f) && (x0f <= (float)(W - 1));
        const bool vx1 = (x1f >= 0.0f) && (x1f <= (float)(W - 1));
        const bool vy0 = (y0f >= 0.0f) && (y0f <= (float)(H - 1));
        const bool vy1 = (y1f >= 0.0f) && (y1f <= (float)(H - 1));

        float m00 = (vx0 && vy0) ? __fmul_rn(wx0, wy0) : 0.0f;
        float m01 = (vx1 && vy0) ? __fmul_rn(wx1, wy0) : 0.0f;
        float m10 = (vx0 && vy1) ? __fmul_rn(wx0, wy1) : 0.0f;
        float m11 = (vx1 && vy1) ? __fmul_rn(wx1, wy1) : 0.0f;

        const float ones_val = __fadd_rn(__fadd_rn(__fadd_rn(m00, m01), m10), m11);
        if (ones_val < 0.99999f) { m00 = m01 = m10 = m11 = 0.0f; }

        const int xi0 = min(max((int)x0f, 0), W - 1);
        const int xi1 = min(max((int)x1f, 0), W - 1);
        const int yi0 = min(max((int)y0f, 0), H - 1);
        const int yi1 = min(max((int)y1f, 0), H - 1);

        sw[lane] = make_float4(m00, m01, m10, m11);
        so[lane] = (yi0 * W + xi0) | ((xi1 - xi0) << 15) | ((yi1 - yi0) << 16);
    }
    __syncthreads();

    const __half* xt = g_xt + (size_t)b * HW * C;
    const int c8   = 8 * li;                           // channel base
    const int colw = 4 * li + 2 * (li >> 3);           // swizzled column word

    #pragma unroll
    for (int t = 0; t < 2; ++t) {
        const int p = warp * 4 + 2 * t + hf;           // this lane's pixel

        const float4 wv = sw[p];
        const int    pk = so[p];

        const int o00 = pk & 0x7FFF;
        const int dx  = (pk >> 15) & 1;
        const int o10 = o00 + ((pk >> 16) & 1) * W;
        const int o01 = o00 + dx;
        const int o11 = o10 + dx;

        // 4 independent 16B corner loads (8 channels each).
        const uint4 r00 = *(const uint4*)(xt + (size_t)o00 * C + c8);
        const uint4 r01 = *(const uint4*)(xt + (size_t)o01 * C + c8);
        const uint4 r10 = *(const uint4*)(xt + (size_t)o10 * C + c8);
        const uint4 r11 = *(const uint4*)(xt + (size_t)o11 * C + c8);

        unsigned* row = stile + RS * p + colw;
        #pragma unroll
        for (int k = 0; k < 4; ++k) {
            const unsigned u00 = (&r00.x)[k];
            const unsigned u01 = (&r01.x)[k];
            const unsigned u10 = (&r10.x)[k];
            const unsigned u11 = (&r11.x)[k];
            const float2 f00 = __half22float2(*(const __half2*)&u00);
            const float2 f01 = __half22float2(*(const __half2*)&u01);
            const float2 f10 = __half22float2(*(const __half2*)&u10);
            const float2 f11 = __half22float2(*(const __half2*)&u11);
            const float va = fmaf(f11.x, wv.w, fmaf(f10.x, wv.z, fmaf(f01.x, wv.y, f00.x * wv.x)));
            const float vb2 = fmaf(f11.y, wv.w, fmaf(f10.y, wv.z, fmaf(f01.y, wv.y, f00.y * wv.x)));
            const __half2 hv = __floats2half2_rn(va, vb2);
            row[k] = *(const unsigned*)&hv;            // conflict-free STS.32
        }
    }

    __syncthreads();

    // Writeback: thread (warp wp, lane p) iterates channel pairs q = wp + 8j.
    const int p  = tid & 31;
    const int wp = tid >> 5;
    float* po = out + (size_t)b * C * HW + (size_t)h * W + w0 + p;
    #pragma unroll
    for (int j = 0; j < 8; ++j) {
        const int q = wp + 8 * j;                      // channel pair
        const unsigned u = stile[RS * p + q + 2 * (q >> 5)];
        const float2 f = __half22float2(*(const __half2*)&u);
        __stcs(po + (size_t)(2 * q) * HW,     f.x);
        __stcs(po + (size_t)(2 * q + 1) * HW, f.y);
    }
}

// ---------------- persistent pipeline kernel ----------------
__global__ __launch_bounds__(256, 7) void persistent_kernel(
    const float* __restrict__ x,
    const float* __restrict__ flow,
    float* __restrict__ out)
{
    __shared__ char smem[32 * 133 * 4];        // 17024 B, both roles overlay
    __shared__ unsigned s_id;

    const int tid = threadIdx.x;

    for (;;) {
        if (tid == 0) s_id = atomicAdd(&g_ctr, 1u);
        __syncthreads();
        const unsigned id = s_id;
        __syncthreads();                       // protect s_id before next claim

        if (id >= NITEMS) return;              // uniform exit

        int role, b, vb;
        if (id < 1024u)        { role = 0; b = 0; vb = (int)id; }
        else if (id >= 15360u) { role = 1; b = 7; vb = (int)(id - 15360u); }
        else {
            const unsigned s   = id - 1024u;
            const unsigned k0  = s >> 11;      // 0..6
            const unsigned off = s & 2047u;
            vb = (int)(off >> 1);
            if (off & 1u) { role = 1; b = (int)k0; }       // G(k0)
            else          { role = 0; b = (int)k0 + 1; }   // T(k0+1)
        }

        if (role == 0) {
            do_transpose(x, b, vb, smem);
            __threadfence();                   // release this thread's stores
            __syncthreads();
            if (tid == 0) atomicAdd(&g_done[b], 1u);
        } else {
            if (tid == 0) {
                volatile unsigned* df = &g_done[b];
                while (*df < 1024u) __nanosleep(200);
            }
            __syncthreads();
            __threadfence();                   // acquire before reading xt
            do_gather(flow, out, b, vb, smem);
        }
    }
}

}  // namespace

extern "C" void kernel_launch(void* const* d_in, const int* in_sizes, int n_in,
                              void* d_out, int out_size) {
    const float* x    = (const float*)d_in[0];
    const float* flow = (const float*)d_in[1];
    float* out        = (float*)d_out;

    reset_kernel<<<1, 1>>>();
    persistent_kernel<<<GRID, 256>>>(x, flow, out);
}

// round 17
// speedup vs baseline: 1.3168x; 1.3168x over previous
#include <cuda_runtime.h>
#include <cuda_fp16.h>

// WarpingLayer v17: serial two-pass (overlap abandoned — 4 schemes lost).
//   Pass 1: transpose x NCHW f32 -> xt NHWC f16; uint2 (4-channel) stores
//           halve STG instruction count; conflict-free smem column reads.
//   Pass 2: gather with in-block param compute (warp 0 -> smem), then per
//           warp BOTH pixel-pairs' 8 uint4 corner loads issued upfront
//           (MLP=8) before the FMA/STS chains; swizzled fp16 staging
//           (stride 67, conflict-free); half2 readback + coalesced STG.32.
// Param math reproduces the JAX reference fp32 op ordering exactly.

namespace {

constexpr int B = 8;
constexpr int C = 128;
constexpr int H = 128;
constexpr int W = 256;
constexpr int HW = H * W;                     // 32768
constexpr int RS = 67;                        // staging row stride (words)

// 67 MB fp16 scratch for the transposed image (__device__ global: allowed).
__device__ __half g_xt[(size_t)B * HW * C];

// ---------------- Pass 1: NCHW f32 -> NHWC f16 transpose ----------------
__global__ __launch_bounds__(256) void transpose_kernel(const float* __restrict__ x)
{
    __shared__ float tile[32][133];
    const int hw0 = blockIdx.x * 128;
    const int c0  = blockIdx.y * 32;
    const int b   = blockIdx.z;
    const int tx  = threadIdx.x & 31;
    const int ty  = threadIdx.x >> 5;          // 0..7

    const float* px = x + (size_t)b * C * HW;
    #pragma unroll
    for (int i = 0; i < 4; ++i) {
        const int cl = ty + i * 8;             // 0..31
        const float4 v = __ldcs((const float4*)(px + (size_t)(c0 + cl) * HW + hw0) + tx);
        float* t = &tile[cl][4 * tx];
        t[0] = v.x; t[1] = v.y; t[2] = v.z; t[3] = v.w;
    }
    __syncthreads();

    // Write 4 channels (uint2) per lane: lanes (cq 0..7, hws 0..3); per hw row
    // 8 lanes x 8B = 64B contiguous. LDS banks (20cq + hws + const)%32: all 32
    // distinct -> conflict-free column reads.
    __half* pt = g_xt + (size_t)b * HW * C;
    const int cq  = tx & 7;                    // channel quad 0..7
    const int hws = tx >> 3;                   // 0..3
    #pragma unroll
    for (int i = 0; i < 4; ++i) {
        const int hwl = i * 32 + ty * 4 + hws;             // 0..127
        const __half2 h0 = __floats2half2_rn(tile[4 * cq + 0][hwl],
                                             tile[4 * cq + 1][hwl]);
        const __half2 h1 = __floats2half2_rn(tile[4 * cq + 2][hwl],
                                             tile[4 * cq + 3][hwl]);
        uint2 u;
        u.x = *(const unsigned*)&h0;
        u.y = *(const unsigned*)&h1;
        *(uint2*)(pt + (size_t)(hw0 + hwl) * C + c0 + 4 * cq) = u;
    }
}

// ---------------- Pass 2: gather, batched corner loads ----------------
__global__ __launch_bounds__(256, 6) void warp_gather_kernel(
    const float* __restrict__ flow,
    float* __restrict__ out)
{
    __shared__ unsigned stile[32 * RS];        // 8576 B staging (half2 words)
    __shared__ float4   sw[32];                // 32 px weights
    __shared__ int      so[32];                // 32 px packed offsets

    const int tid  = threadIdx.x;
    const int warp = tid >> 5;
    const int lane = tid & 31;
    const int li   = lane & 15;
    const int hf   = lane >> 4;                // 0: pixel A-half, 1: B-half

    const int pix = ((int)gridDim.x - 1 - (int)blockIdx.x) * 32;  // reversed
    const int b  = pix >> 15;
    const int h  = (pix >> 8) & (H - 1);
    const int w0 = pix & (W - 1);

    // ---- warp 0: params for the block's 32 pixels (lane = pixel) ----
    if (warp == 0) {
        const int w = w0 + lane;
        const int fbase = b * 2 * HW + h * W + w;
        const float fx = __ldg(flow + fbase);
        const float fy = __ldg(flow + fbase + HW);

        // Reference-exact fp32 ordering:
        const float flo_w = __fmul_rn(__fdiv_rn(__fmul_rn(fx, 2.0f), (float)(W - 1)), 1.0f);
        const float flo_h = __fmul_rn(__fdiv_rn(__fmul_rn(fy, 2.0f), (float)(H - 1)), 1.0f);
        const float step_x = __fdiv_rn(2.0f, (float)(W - 1));
        const float step_y = __fdiv_rn(2.0f, (float)(H - 1));
        const float gx = __fadd_rn(-1.0f, __fmul_rn((float)w, step_x));
        const float gy = __fadd_rn(-1.0f, __fmul_rn((float)h, step_y));

        const float ix = __fmul_rn(__fmul_rn(__fadd_rn(__fadd_rn(gx, flo_w), 1.0f), 0.5f), (float)(W - 1));
        const float iy = __fmul_rn(__fmul_rn(__fadd_rn(__fadd_rn(gy, flo_h), 1.0f), 0.5f), (float)(H - 1));

        const float x0f = floorf(ix);
        const float y0f = floorf(iy);
        const float x1f = __fadd_rn(x0f, 1.0f);
        const float y1f = __fadd_rn(y0f, 1.0f);

        const float wx1 = __fadd_rn(ix, -x0f);
        const float wx0 = __fadd_rn(1.0f, -wx1);
        const float wy1 = __fadd_rn(iy, -y0f);
        const float wy0 = __fadd_rn(1.0f, -wy1);

        const bool vx0 = (x0f >= 0.0f) && (x0f <= (float)(W - 1));
        const bool vx1 = (x1f >= 0.0f) && (x1f <= (float)(W - 1));
        const bool vy0 = (y0f >= 0.0f) && (y0f <= (float)(H - 1));
        const bool vy1 = (y1f >= 0.0f) && (y1f <= (float)(H - 1));

        float m00 = (vx0 && vy0) ? __fmul_rn(wx0, wy0) : 0.0f;
        float m01 = (vx1 && vy0) ? __fmul_rn(wx1, wy0) : 0.0f;
        float m10 = (vx0 && vy1) ? __fmul_rn(wx0, wy1) : 0.0f;
        float m11 = (vx1 && vy1) ? __fmul_rn(wx1, wy1) : 0.0f;

        const float ones_val = __fadd_rn(__fadd_rn(__fadd_rn(m00, m01), m10), m11);
        if (ones_val < 0.99999f) { m00 = m01 = m10 = m11 = 0.0f; }

        const int xi0 = min(max((int)x0f, 0), W - 1);
        const int xi1 = min(max((int)x1f, 0), W - 1);
        const int yi0 = min(max((int)y0f, 0), H - 1);
        const int yi1 = min(max((int)y1f, 0), H - 1);

        sw[lane] = make_float4(m00, m01, m10, m11);
        so[lane] = (yi0 * W + xi0) | ((xi1 - xi0) << 15) | ((yi1 - yi0) << 16);
    }
    __syncthreads();

    const __half* xt = g_xt + (size_t)b * HW * C;
    const int c8   = 8 * li;                           // channel base
    const int colw = 4 * li + 2 * (li >> 3);           // swizzled column word

    // This lane's two pixels.
    const int pA = warp * 4 + hf;
    const int pB = pA + 2;

    const float4 wvA = sw[pA];
    const float4 wvB = sw[pB];
    const int    kA  = so[pA];
    const int    kB  = so[pB];

    const int a00 = kA & 0x7FFF;
    const int adx = (kA >> 15) & 1;
    const int a10 = a00 + ((kA >> 16) & 1) * W;
    const int a01 = a00 + adx;
    const int a11 = a10 + adx;

    const int b00 = kB & 0x7FFF;
    const int bdx = (kB >> 15) & 1;
    const int b10 = b00 + ((kB >> 16) & 1) * W;
    const int b01 = b00 + bdx;
    const int b11 = b10 + bdx;

    // 8 independent 16B corner loads issued together (MLP = 8).
    const uint4 rA00 = *(const uint4*)(xt + (size_t)a00 * C + c8);
    const uint4 rA01 = *(const uint4*)(xt + (size_t)a01 * C + c8);
    const uint4 rA10 = *(const uint4*)(xt + (size_t)a10 * C + c8);
    const uint4 rA11 = *(const uint4*)(xt + (size_t)a11 * C + c8);
    const uint4 rB00 = *(const uint4*)(xt + (size_t)b00 * C + c8);
    const uint4 rB01 = *(const uint4*)(xt + (size_t)b01 * C + c8);
    const uint4 rB10 = *(const uint4*)(xt + (size_t)b10 * C + c8);
    const uint4 rB11 = *(const uint4*)(xt + (size_t)b11 * C + c8);

    unsigned* rowA = stile + RS * pA + colw;
    unsigned* rowB = stile + RS * pB + colw;
    #pragma unroll
    for (int k = 0; k < 4; ++k) {
        {
            const unsigned u00 = (&rA00.x)[k], u01 = (&rA01.x)[k];
            const unsigned u10 = (&rA10.x)[k], u11 = (&rA11.x)[k];
            const float2 f00 = __half22float2(*(const __half2*)&u00);
            const float2 f01 = __half22float2(*(const __half2*)&u01);
            const float2 f10 = __half22float2(*(const __half2*)&u10);
            const float2 f11 = __half22float2(*(const __half2*)&u11);
            const float va = fmaf(f11.x, wvA.w, fmaf(f10.x, wvA.z, fmaf(f01.x, wvA.y, f00.x * wvA.x)));
            const float vb = fmaf(f11.y, wvA.w, fmaf(f10.y, wvA.z, fmaf(f01.y, wvA.y, f00.y * wvA.x)));
            const __half2 hv = __floats2half2_rn(va, vb);
            rowA[k] = *(const unsigned*)&hv;           // conflict-free STS.32
        }
        {
            const unsigned u00 = (&rB00.x)[k], u01 = (&rB01.x)[k];
            const unsigned u10 = (&rB10.x)[k], u11 = (&rB11.x)[k];
            const float2 f00 = __half22float2(*(const __half2*)&u00);
            const float2 f01 = __half22float2(*(const __half2*)&u01);
            const float2 f10 = __half22float2(*(const __half2*)&u10);
            const float2 f11 = __half22float2(*(const __half2*)&u11);
            const float va = fmaf(f11.x, wvB.w, fmaf(f10.x, wvB.z, fmaf(f01.x, wvB.y, f00.x * wvB.x)));
            const float vb = fmaf(f11.y, wvB.w, fmaf(f10.y, wvB.z, fmaf(f01.y, wvB.y, f00.y * wvB.x)));
            const __half2 hv = __floats2half2_rn(va, vb);
            rowB[k] = *(const unsigned*)&hv;           // conflict-free STS.32
        }
    }

    __syncthreads();

    // Writeback: thread (warp wp, lane p) iterates channel pairs q = wp + 8j.
    // LDS word RS*p + q + 2*(q>>5): bank (3p + const)%32 -> conflict-free.
    // Two coalesced STG.32 per pair (lanes = consecutive w).
    const int p  = tid & 31;
    const int wp = tid >> 5;
    float* po = out + (size_t)b * C * HW + (size_t)h * W + w0 + p;
    #pragma unroll
    for (int j = 0; j < 8; ++j) {
        const int q = wp + 8 * j;                      // channel pair
        const unsigned u = stile[RS * p + q + 2 * (q >> 5)];
        const float2 f = __half22float2(*(const __half2*)&u);
        __stcs(po + (size_t)(2 * q) * HW,     f.x);
        __stcs(po + (size_t)(2 * q + 1) * HW, f.y);
    }
}

}  // namespace

extern "C" void kernel_launch(void* const* d_in, const int* in_sizes, int n_in,
                              void* d_out, int out_size) {
    const float* x    = (const float*)d_in[0];
    const float* flow = (const float*)d_in[1];
    float* out        = (float*)d_out;

    dim3 tgrid(HW / 128, C / 32, B);           // (256, 4, 8)
    transpose_kernel<<<tgrid, 256>>>(x);

    const int nblocks = (B * HW) / 32;         // 8192
    warp_gather_kernel<<<nblocks, 256>>>(flow, out);
}